// round 14
// baseline (speedup 1.0000x reference)
#include <cuda_runtime.h>
#include <cuda_bf16.h>
#include <math.h>
#include <stdint.h>

#define N_LAYERS 4
#define N_EMBD   1024
#define D_INNER  2048
#define D_STATE  16
#define DT_RANK  64
#define D_CONV   4
#define VOCAB    50257
#define SEQLEN   2048
#define XPROJ_N  (DT_RANK + 2 * D_STATE)   // 96

// ================= scratch (allocation-free: __device__ globals) =================
// fp32
__device__ __align__(16) float g_x    [SEQLEN * N_EMBD];        // residual stream
__device__ __align__(16) float g_xr   [SEQLEN * 2 * D_INNER];   // in_proj out [xc | res]
__device__ __align__(16) float g_xc   [SEQLEN * D_INNER];       // conv+silu (u)
__device__ __align__(16) float g_xdbl [SEQLEN * XPROJ_N];       // [dt | B | C]
__device__ __align__(16) float g_delta[SEQLEN * D_INNER];
// bf16 hi/lo activations (GEMM A operands)
__device__ __align__(16) __nv_bfloat16 g_h_hi   [SEQLEN * N_EMBD];
__device__ __align__(16) __nv_bfloat16 g_h_lo   [SEQLEN * N_EMBD];
__device__ __align__(16) __nv_bfloat16 g_xc_hi  [SEQLEN * D_INNER];
__device__ __align__(16) __nv_bfloat16 g_xc_lo  [SEQLEN * D_INNER];
__device__ __align__(16) __nv_bfloat16 g_xdbl_hi[SEQLEN * XPROJ_N];
__device__ __align__(16) __nv_bfloat16 g_xdbl_lo[SEQLEN * XPROJ_N];
__device__ __align__(16) __nv_bfloat16 g_y_hi   [SEQLEN * D_INNER];
__device__ __align__(16) __nv_bfloat16 g_y_lo   [SEQLEN * D_INNER];
// bf16 hi/lo weights (GEMM B operands)
__device__ __align__(16) __nv_bfloat16 g_wemb_hi[VOCAB * N_EMBD];
__device__ __align__(16) __nv_bfloat16 g_wemb_lo[VOCAB * N_EMBD];
__device__ __align__(16) __nv_bfloat16 g_win_hi [N_LAYERS * 2 * D_INNER * N_EMBD];
__device__ __align__(16) __nv_bfloat16 g_win_lo [N_LAYERS * 2 * D_INNER * N_EMBD];
__device__ __align__(16) __nv_bfloat16 g_wxp_hi [N_LAYERS * XPROJ_N * D_INNER];
__device__ __align__(16) __nv_bfloat16 g_wxp_lo [N_LAYERS * XPROJ_N * D_INNER];
__device__ __align__(16) __nv_bfloat16 g_wdt_hi [N_LAYERS * D_INNER * DT_RANK];
__device__ __align__(16) __nv_bfloat16 g_wdt_lo [N_LAYERS * D_INNER * DT_RANK];
__device__ __align__(16) __nv_bfloat16 g_wout_hi[N_LAYERS * N_EMBD * D_INNER];
__device__ __align__(16) __nv_bfloat16 g_wout_lo[N_LAYERS * N_EMBD * D_INNER];

// ================= helpers =================
__device__ __forceinline__ float siluf(float x)     { return x * (1.f / (1.f + __expf(-x))); }
__device__ __forceinline__ float softplusf(float x) { return (x > 20.f) ? x : log1pf(expf(x)); }

__device__ __forceinline__ void split_write(float v, __nv_bfloat16* hi, __nv_bfloat16* lo, size_t idx) {
    __nv_bfloat16 h = __float2bfloat16(v);
    hi[idx] = h;
    lo[idx] = __float2bfloat16(v - __bfloat162float(h));
}

__device__ __forceinline__ uint32_t smem_u32(const void* p) {
    uint32_t a;
    asm("{ .reg .u64 t; cvta.to.shared.u64 t, %1; cvt.u32.u64 %0, t; }" : "=r"(a) : "l"(p));
    return a;
}

__device__ __forceinline__ void cpa16(uint32_t dst, const void* src, bool pred) {
    int sz = pred ? 16 : 0;
    asm volatile("cp.async.ca.shared.global [%0], [%1], 16, %2;"
                 :: "r"(dst), "l"(src), "r"(sz) : "memory");
}
#define CP_COMMIT() asm volatile("cp.async.commit_group;" ::: "memory")
#define CP_WAIT1()  asm volatile("cp.async.wait_group 1;" ::: "memory")
#define CP_WAIT0()  asm volatile("cp.async.wait_group 0;" ::: "memory")

__device__ __forceinline__ void ldmx4(uint32_t addr, uint32_t r[4]) {
    asm volatile("ldmatrix.sync.aligned.m8n8.x4.shared.b16 {%0,%1,%2,%3}, [%4];"
                 : "=r"(r[0]), "=r"(r[1]), "=r"(r[2]), "=r"(r[3]) : "r"(addr));
}

__device__ __forceinline__ void mma16816(float d[4], const uint32_t a[4], const uint32_t b[2]) {
    asm volatile("mma.sync.aligned.m16n8k16.row.col.f32.bf16.bf16.f32 "
                 "{%0,%1,%2,%3}, {%4,%5,%6,%7}, {%8,%9}, {%0,%1,%2,%3};"
                 : "+f"(d[0]), "+f"(d[1]), "+f"(d[2]), "+f"(d[3])
                 : "r"(a[0]), "r"(a[1]), "r"(a[2]), "r"(a[3]), "r"(b[0]), "r"(b[1]));
}

// ================= mma.sync GEMM, bf16 hi/lo pre-split, 2-stage cp.async =================
// C[M,N] = A[M,K] @ W[N,K]^T.  Grid (M/128, ceil(N/128)), 256 threads (8 warps, 2x4).
// BK=32 (K % 32 == 0).  Rows in smem padded 64B->80B (conflict-free ldmatrix).
// EPI: 0 plain fp32; 1 softplus(v+bias); 2 v+Cadd; 3 fp32 + hi/lo split write
static constexpr int STAGE_BYTES = 4 * 128 * 80;            // Ah,Al,Bh,Bl = 40960
static constexpr int GEMM_SMEM   = 2 * STAGE_BYTES;         // 81920 >= epilogue 66048

template<int EPI>
__global__ __launch_bounds__(256, 2)
void mma_gemm(const __nv_bfloat16* __restrict__ Ahi, const __nv_bfloat16* __restrict__ Alo, int lda,
              const __nv_bfloat16* __restrict__ Whi, const __nv_bfloat16* __restrict__ Wlo,
              const float* __restrict__ bias,
              const float* __restrict__ Cadd,
              float* __restrict__ C,
              __nv_bfloat16* __restrict__ Chi, __nv_bfloat16* __restrict__ Clo,
              int ldc, int N, int K)
{
    extern __shared__ char smem[];
    const uint32_t sb = smem_u32(smem);
    const int tid  = threadIdx.x;
    const int lane = tid & 31;
    const int wid  = tid >> 5;
    const int wy   = wid >> 2, wx = wid & 3;      // warp grid 2 x 4 (64 x 32 tiles)
    const int row0 = blockIdx.x * 128;
    const int col0 = blockIdx.y * 128;

    // per-stage matrix offsets (within stage): Ah 0, Al 10240, Bh 20480, Bl 30720
    // loader: 2048 16B-segs per stage, 8 per thread: seg = tid + 256*q
    // seg -> mat (seg>>9), idx (seg&511): r = idx>>2, s = idx&3
    // ldmatrix lane offsets
    const uint32_t aoff = (uint32_t)((wy * 64 + (lane & 15)) * 80 + (lane >> 4) * 16);
    const uint32_t boff = (uint32_t)((wx * 32 + ((lane >> 4) << 3) + (lane & 7)) * 80
                                     + ((lane >> 3) & 1) * 16);

    float acc[4][4][4];
    #pragma unroll
    for (int i = 0; i < 4; ++i)
        #pragma unroll
        for (int j = 0; j < 4; ++j)
            #pragma unroll
            for (int r = 0; r < 4; ++r) acc[i][j][r] = 0.f;

    const int NC = K >> 5;   // BK = 32

    // ---- chunk copy: global bf16 -> smem stage via cp.async ----
    auto copy_chunk = [&](int c, int stage) {
        const int k0 = c << 5;
        const uint32_t stb = sb + stage * STAGE_BYTES;
        #pragma unroll
        for (int q = 0; q < 8; ++q) {
            int seg = tid + (q << 8);
            int mat = seg >> 9;
            int idx = seg & 511;
            int r = idx >> 2, s = idx & 3;
            uint32_t dst = stb + mat * 10240 + r * 80 + s * 16;
            if (mat == 0) {
                cpa16(dst, Ahi + (size_t)(row0 + r) * lda + k0 + s * 8, true);
            } else if (mat == 1) {
                cpa16(dst, Alo + (size_t)(row0 + r) * lda + k0 + s * 8, true);
            } else {
                bool ok = (col0 + r) < N;
                int rr = ok ? (col0 + r) : 0;
                const __nv_bfloat16* src = (mat == 2) ? Whi : Wlo;
                cpa16(dst, src + (size_t)rr * K + k0 + s * 8, ok);
            }
        }
    };

    copy_chunk(0, 0);
    CP_COMMIT();

    for (int c = 0; c < NC; ++c) {
        if (c + 1 < NC) {
            copy_chunk(c + 1, (c + 1) & 1);
            CP_COMMIT();
            CP_WAIT1();
        } else {
            CP_WAIT0();
        }
        __syncthreads();

        const uint32_t stb = sb + (c & 1) * STAGE_BYTES;
        const uint32_t aAh = stb + aoff, aAl = stb + 10240 + aoff;
        const uint32_t bBh = stb + 20480 + boff, bBl = stb + 30720 + boff;

        #pragma unroll
        for (int kb = 0; kb < 2; ++kb) {
            const uint32_t kby = kb * 32;   // 16 bf16 = 32 bytes per k-step
            uint32_t bh[4][2], bl[4][2];
            {
                uint32_t t[4];
                ldmx4(bBh + kby, t);        bh[0][0]=t[0]; bh[0][1]=t[1]; bh[1][0]=t[2]; bh[1][1]=t[3];
                ldmx4(bBh + kby + 1280, t); bh[2][0]=t[0]; bh[2][1]=t[1]; bh[3][0]=t[2]; bh[3][1]=t[3];
                ldmx4(bBl + kby, t);        bl[0][0]=t[0]; bl[0][1]=t[1]; bl[1][0]=t[2]; bl[1][1]=t[3];
                ldmx4(bBl + kby + 1280, t); bl[2][0]=t[0]; bl[2][1]=t[1]; bl[3][0]=t[2]; bl[3][1]=t[3];
            }
            #pragma unroll
            for (int i = 0; i < 4; ++i) {
                uint32_t ah[4], al[4];
                ldmx4(aAh + i * 1280 + kby, ah);
                ldmx4(aAl + i * 1280 + kby, al);
                #pragma unroll
                for (int j = 0; j < 4; ++j) {
                    mma16816(acc[i][j], ah, bh[j]);
                    mma16816(acc[i][j], ah, bl[j]);
                    mma16816(acc[i][j], al, bh[j]);
                }
            }
        }
        __syncthreads();
    }

    // ---- epilogue: stage fp32 through smem (reuse tile space), coalesced stores ----
    float* eb = (float*)smem;
    #pragma unroll
    for (int i = 0; i < 4; ++i) {
        #pragma unroll
        for (int j = 0; j < 4; ++j) {
            int r = wy * 64 + i * 16 + (lane >> 2);
            int c = wx * 32 + j * 8 + (lane & 3) * 2;
            eb[r * 129 + c]           = acc[i][j][0];
            eb[r * 129 + c + 1]       = acc[i][j][1];
            eb[(r + 8) * 129 + c]     = acc[i][j][2];
            eb[(r + 8) * 129 + c + 1] = acc[i][j][3];
        }
    }
    __syncthreads();

    const int cl = tid & 127;
    const int cc = col0 + cl;
    const bool cok = cc < N;
    float bv = 0.f;
    if (EPI == 1 && cok) bv = bias[cc];
    const int rbase = (tid >> 7) * 64;
    for (int kk = 0; kk < 64; ++kk) {
        const int r = row0 + rbase + kk;
        float v = eb[(rbase + kk) * 129 + cl];
        if (cok) {
            if (EPI == 1) v = softplusf(v + bv);
            if (EPI == 2) v += Cadd[(size_t)r * ldc + cc];
            if (EPI == 3) {
                __nv_bfloat16 hh = __float2bfloat16(v);
                Chi[(size_t)r * ldc + cc] = hh;
                Clo[(size_t)r * ldc + cc] = __float2bfloat16(v - __bfloat162float(hh));
            }
            C[(size_t)r * ldc + cc] = v;
        }
    }
}

// ================= fp32 -> bf16 hi/lo splitter (weights) =================
__global__ void split_kernel(const float* __restrict__ s,
                             __nv_bfloat16* __restrict__ hi,
                             __nv_bfloat16* __restrict__ lo, int n4) {
    int i = blockIdx.x * blockDim.x + threadIdx.x;
    if (i >= n4) return;
    float4 v = ((const float4*)s)[i];
    size_t b = (size_t)i * 4;
    split_write(v.x, hi, lo, b + 0);
    split_write(v.y, hi, lo, b + 1);
    split_write(v.z, hi, lo, b + 2);
    split_write(v.w, hi, lo, b + 3);
}

// ================= embedding =================
__global__ void embed_kernel(const int* __restrict__ tokens,
                             const float* __restrict__ embW,
                             float* __restrict__ x) {
    int idx = blockIdx.x * blockDim.x + threadIdx.x;
    int t = idx >> 10;
    int e = idx & 1023;
    x[idx] = embW[(size_t)tokens[t] * N_EMBD + e];
}

// ================= rmsnorm -> hi/lo bf16 =================
__global__ void rmsnorm_kernel(const float* __restrict__ x,
                               const float* __restrict__ w,
                               const float* __restrict__ b,
                               __nv_bfloat16* __restrict__ ohi,
                               __nv_bfloat16* __restrict__ olo) {
    int row = blockIdx.x;
    const float* xr = x + (size_t)row * N_EMBD;
    float s = 0.f;
    for (int i = threadIdx.x; i < N_EMBD; i += blockDim.x) {
        float v = xr[i];
        s += v * v;
    }
    __shared__ float red[32];
    int lane = threadIdx.x & 31, wid = threadIdx.x >> 5;
    #pragma unroll
    for (int o = 16; o; o >>= 1) s += __shfl_xor_sync(0xffffffffu, s, o);
    if (lane == 0) red[wid] = s;
    __syncthreads();
    if (wid == 0) {
        s = (lane < (blockDim.x >> 5)) ? red[lane] : 0.f;
        #pragma unroll
        for (int o = 16; o; o >>= 1) s += __shfl_xor_sync(0xffffffffu, s, o);
        if (lane == 0) red[0] = s;
    }
    __syncthreads();
    float inv = rsqrtf(red[0] * (1.f / N_EMBD) + 1e-6f);
    for (int i = threadIdx.x; i < N_EMBD; i += blockDim.x) {
        float v = xr[i] * inv * w[i] + b[i];
        split_write(v, ohi, olo, (size_t)row * N_EMBD + i);
    }
}

// ================= depthwise causal conv (k=4) + silu -> fp32 + hi/lo =================
__global__ void conv_silu_kernel(const float* __restrict__ xr,
                                 const float* __restrict__ cw,
                                 const float* __restrict__ cb,
                                 float* __restrict__ xc,
                                 __nv_bfloat16* __restrict__ xchi,
                                 __nv_bfloat16* __restrict__ xclo) {
    int idx = blockIdx.x * blockDim.x + threadIdx.x;
    int d = idx & (D_INNER - 1);
    int t = idx >> 11;
    const float* w = cw + d * D_CONV;
    float acc = cb[d];
    #pragma unroll
    for (int k = 0; k < D_CONV; ++k) {
        int tt = t - (D_CONV - 1) + k;
        if (tt >= 0) acc += w[k] * xr[(size_t)tt * (2 * D_INNER) + d];
    }
    float v = siluf(acc);
    xc[idx] = v;
    split_write(v, xchi, xclo, idx);
}

// ================= selective scan -> y hi/lo =================
__global__ __launch_bounds__(256)
void scan_kernel(const float* __restrict__ u,
                 const float* __restrict__ delta,
                 const float* __restrict__ Alog,
                 const float* __restrict__ Bm,
                 const float* __restrict__ Cm,
                 int ldbc,
                 const float* __restrict__ Dp,
                 const float* __restrict__ res,
                 int ldres,
                 __nv_bfloat16* __restrict__ yhi,
                 __nv_bfloat16* __restrict__ ylo)
{
    int idx = blockIdx.x * blockDim.x + threadIdx.x;
    int d = idx >> 4;
    int n = idx & 15;
    float A = -expf(Alog[d * D_STATE + n]);
    float Dd = Dp[d];
    float s = 0.f;

    #pragma unroll 4
    for (int t = 0; t < SEQLEN; ++t) {
        float dlt = delta[(size_t)t * D_INNER + d];
        float uu  = u[(size_t)t * D_INNER + d];
        float Bt  = Bm[(size_t)t * ldbc + n];
        float Ct  = Cm[(size_t)t * ldbc + n];
        s = expf(dlt * A) * s + dlt * Bt * uu;
        float yv = s * Ct;
        yv += __shfl_xor_sync(0xffffffffu, yv, 1);
        yv += __shfl_xor_sync(0xffffffffu, yv, 2);
        yv += __shfl_xor_sync(0xffffffffu, yv, 4);
        yv += __shfl_xor_sync(0xffffffffu, yv, 8);
        if (n == 0) {
            float r = res[(size_t)t * ldres + d];
            float yo = (yv + uu * Dd) * siluf(r);
            split_write(yo, yhi, ylo, (size_t)t * D_INNER + d);
        }
    }
}

// ================= host orchestration =================
extern "C" void kernel_launch(void* const* d_in, const int* in_sizes, int n_in,
                              void* d_out, int out_size) {
    const int*   tokens   = (const int*)  d_in[0];
    const float* emb_W    = (const float*)d_in[1];   // [VOCAB, N_EMBD]
    const float* in_proj  = (const float*)d_in[2];   // [4, 2*D_INNER, N_EMBD]
    const float* conv_W   = (const float*)d_in[3];   // [4, D_INNER, 1, 4]
    const float* conv_b   = (const float*)d_in[4];   // [4, D_INNER]
    const float* xproj_W  = (const float*)d_in[5];   // [4, 96, D_INNER]
    const float* dt_W     = (const float*)d_in[6];   // [4, D_INNER, 64]
    const float* dt_b     = (const float*)d_in[7];   // [4, D_INNER]
    const float* A_log    = (const float*)d_in[8];   // [4, D_INNER, 16]
    const float* Dp       = (const float*)d_in[9];   // [4, D_INNER]
    const float* out_W    = (const float*)d_in[10];  // [4, N_EMBD, D_INNER]
    const float* rms_w    = (const float*)d_in[11];
    const float* rms_b    = (const float*)d_in[12];
    const float* normf_w  = (const float*)d_in[13];
    const float* normf_b  = (const float*)d_in[14];
    float* out = (float*)d_out;                      // [SEQLEN, VOCAB]

    // idempotent, non-stream host calls (no static guard: determinism rule)
    cudaFuncSetAttribute(mma_gemm<0>, cudaFuncAttributeMaxDynamicSharedMemorySize, GEMM_SMEM);
    cudaFuncSetAttribute(mma_gemm<1>, cudaFuncAttributeMaxDynamicSharedMemorySize, GEMM_SMEM);
    cudaFuncSetAttribute(mma_gemm<2>, cudaFuncAttributeMaxDynamicSharedMemorySize, GEMM_SMEM);
    cudaFuncSetAttribute(mma_gemm<3>, cudaFuncAttributeMaxDynamicSharedMemorySize, GEMM_SMEM);

    float *x, *xr, *xc, *xdbl, *dlt;
    __nv_bfloat16 *h_hi, *h_lo, *xc_hi, *xc_lo, *xd_hi, *xd_lo, *y_hi, *y_lo;
    __nv_bfloat16 *we_hi, *we_lo, *wi_hi, *wi_lo, *wx_hi, *wx_lo, *wd_hi, *wd_lo, *wo_hi, *wo_lo;
    cudaGetSymbolAddress((void**)&x,     g_x);
    cudaGetSymbolAddress((void**)&xr,    g_xr);
    cudaGetSymbolAddress((void**)&xc,    g_xc);
    cudaGetSymbolAddress((void**)&xdbl,  g_xdbl);
    cudaGetSymbolAddress((void**)&dlt,   g_delta);
    cudaGetSymbolAddress((void**)&h_hi,  g_h_hi);    cudaGetSymbolAddress((void**)&h_lo,  g_h_lo);
    cudaGetSymbolAddress((void**)&xc_hi, g_xc_hi);   cudaGetSymbolAddress((void**)&xc_lo, g_xc_lo);
    cudaGetSymbolAddress((void**)&xd_hi, g_xdbl_hi); cudaGetSymbolAddress((void**)&xd_lo, g_xdbl_lo);
    cudaGetSymbolAddress((void**)&y_hi,  g_y_hi);    cudaGetSymbolAddress((void**)&y_lo,  g_y_lo);
    cudaGetSymbolAddress((void**)&we_hi, g_wemb_hi); cudaGetSymbolAddress((void**)&we_lo, g_wemb_lo);
    cudaGetSymbolAddress((void**)&wi_hi, g_win_hi);  cudaGetSymbolAddress((void**)&wi_lo, g_win_lo);
    cudaGetSymbolAddress((void**)&wx_hi, g_wxp_hi);  cudaGetSymbolAddress((void**)&wx_lo, g_wxp_lo);
    cudaGetSymbolAddress((void**)&wd_hi, g_wdt_hi);  cudaGetSymbolAddress((void**)&wd_lo, g_wdt_lo);
    cudaGetSymbolAddress((void**)&wo_hi, g_wout_hi); cudaGetSymbolAddress((void**)&wo_lo, g_wout_lo);

    // weight splits (once per launch; deterministic)
    {
        int n4;
        n4 = VOCAB * N_EMBD / 4;
        split_kernel<<<(n4 + 255) / 256, 256>>>(emb_W, we_hi, we_lo, n4);
        n4 = N_LAYERS * 2 * D_INNER * N_EMBD / 4;
        split_kernel<<<(n4 + 255) / 256, 256>>>(in_proj, wi_hi, wi_lo, n4);
        n4 = N_LAYERS * XPROJ_N * D_INNER / 4;
        split_kernel<<<(n4 + 255) / 256, 256>>>(xproj_W, wx_hi, wx_lo, n4);
        n4 = N_LAYERS * D_INNER * DT_RANK / 4;
        split_kernel<<<(n4 + 255) / 256, 256>>>(dt_W, wd_hi, wd_lo, n4);
        n4 = N_LAYERS * N_EMBD * D_INNER / 4;
        split_kernel<<<(n4 + 255) / 256, 256>>>(out_W, wo_hi, wo_lo, n4);
    }

    embed_kernel<<<(SEQLEN * N_EMBD) / 256, 256>>>(tokens, emb_W, x);

    for (int i = 0; i < N_LAYERS; ++i) {
        // h = rmsnorm(x) -> hi/lo
        rmsnorm_kernel<<<SEQLEN, 256>>>(x, rms_w + i * N_EMBD, rms_b + i * N_EMBD, h_hi, h_lo);

        // xr = h @ in_proj[i]^T   [2048, 4096]
        mma_gemm<0><<<dim3(SEQLEN / 128, 2 * D_INNER / 128), 256, GEMM_SMEM>>>(
            h_hi, h_lo, N_EMBD,
            wi_hi + (size_t)i * 2 * D_INNER * N_EMBD, wi_lo + (size_t)i * 2 * D_INNER * N_EMBD,
            nullptr, nullptr, xr, nullptr, nullptr, 2 * D_INNER, 2 * D_INNER, N_EMBD);

        // xc = silu(causal_conv(xr[:, :D_INNER])) -> fp32 + hi/lo
        conv_silu_kernel<<<(SEQLEN * D_INNER) / 256, 256>>>(
            xr, conv_W + (size_t)i * D_INNER * D_CONV, conv_b + (size_t)i * D_INNER,
            xc, xc_hi, xc_lo);

        // x_dbl = xc @ xproj[i]^T   [2048, 96] -> fp32 + hi/lo
        mma_gemm<3><<<dim3(SEQLEN / 128, 1), 256, GEMM_SMEM>>>(
            xc_hi, xc_lo, D_INNER,
            wx_hi + (size_t)i * XPROJ_N * D_INNER, wx_lo + (size_t)i * XPROJ_N * D_INNER,
            nullptr, nullptr, xdbl, xd_hi, xd_lo, XPROJ_N, XPROJ_N, D_INNER);

        // delta = softplus(x_dbl[:, :64] @ dt_W[i]^T + dt_b[i])   [2048, 2048]
        mma_gemm<1><<<dim3(SEQLEN / 128, D_INNER / 128), 256, GEMM_SMEM>>>(
            xd_hi, xd_lo, XPROJ_N,
            wd_hi + (size_t)i * D_INNER * DT_RANK, wd_lo + (size_t)i * D_INNER * DT_RANK,
            dt_b + (size_t)i * D_INNER, nullptr, dlt, nullptr, nullptr, D_INNER, D_INNER, DT_RANK);

        // selective scan (fused: + u*D, * silu(res)) -> y hi/lo
        scan_kernel<<<(D_INNER * D_STATE) / 256, 256>>>(
            xc, dlt, A_log + (size_t)i * D_INNER * D_STATE,
            xdbl + DT_RANK, xdbl + DT_RANK + D_STATE, XPROJ_N,
            Dp + (size_t)i * D_INNER, xr + D_INNER, 2 * D_INNER, y_hi, y_lo);

        // x = x + y @ out_W[i]^T   [2048, 1024]
        mma_gemm<2><<<dim3(SEQLEN / 128, N_EMBD / 128), 256, GEMM_SMEM>>>(
            y_hi, y_lo, D_INNER,
            wo_hi + (size_t)i * N_EMBD * D_INNER, wo_lo + (size_t)i * N_EMBD * D_INNER,
            nullptr, x, x, nullptr, nullptr, N_EMBD, N_EMBD, D_INNER);
    }

    // final norm + tied LM head
    rmsnorm_kernel<<<SEQLEN, 256>>>(x, normf_w, normf_b, h_hi, h_lo);
    mma_gemm<0><<<dim3(SEQLEN / 128, (VOCAB + 127) / 128), 256, GEMM_SMEM>>>(
        h_hi, h_lo, N_EMBD, we_hi, we_lo,
        nullptr, nullptr, out, nullptr, nullptr, VOCAB, VOCAB, N_EMBD);
}